// round 6
// baseline (speedup 1.0000x reference)
#include <cuda_runtime.h>

// SurfNetwork: grid-feature gather + tiny color MLP + volume rendering.
// One warp per ray. Lane L handles samples 4L..4L+3.
// Gathers go through cp.async.cg (16B, L1-bypass) into shared memory so the
// in-flight data does not consume registers -> higher occupancy -> more MLP.
// Gathers to the first PIN_ROWS of the table are tagged L2::evict_last so that
// slice of the 256MB table stays resident in L2 across graph replays.
//
// Inputs: x i32[B,128,2], d f32[B,16], gridWeight f32[16M,4], W0 f32[22,8], W1 f32[8,3]
// Output: concat(sigma[B*128], rgb[B*3]) f32.

#define RAY_N    128
#define WPB      8                      // warps per block (256 threads)
#define PIN_ROWS (4u << 20)             // 4M rows * 16B = 64MB pinned slice

__global__ __launch_bounds__(256, 4) void surf_kernel(
    const int*    __restrict__ x,
    const float*  __restrict__ dvec,
    const float4* __restrict__ gw,
    const float*  __restrict__ W0,
    const float*  __restrict__ W1,
    float*        __restrict__ sigma_out,
    float*        __restrict__ rgb_out,
    int B)
{
    __shared__ float  sW0[22 * 8];
    __shared__ float  sW1[8 * 3];
    __shared__ float4 buf[WPB][8][32];   // [warp][slot][lane], 32KB

    int tid = threadIdx.x;
    if (tid < 176) sW0[tid] = W0[tid];
    if (tid < 24)  sW1[tid] = W1[tid];
    __syncthreads();

    int warp = (int)((blockIdx.x * blockDim.x + tid) >> 5);
    if (warp >= B) return;
    int lane = tid & 31;
    int wloc = (tid >> 5);

    // ---- index load: 8 consecutive ints per lane (2 x int4, coalesced) ----
    const int4* xr = (const int4*)(x + (size_t)warp * (RAY_N * 2));
    int4 xa = __ldg(&xr[lane * 2]);
    int4 xb = __ldg(&xr[lane * 2 + 1]);

    // ---- L2 cache policies ----
    unsigned long long polLast, polNorm;
    asm volatile("createpolicy.fractional.L2::evict_last.b64 %0, 1.0;"   : "=l"(polLast));
    asm volatile("createpolicy.fractional.L2::evict_normal.b64 %0, 1.0;" : "=l"(polNorm));

    // ---- issue all 8 random gathers via cp.async as early as possible ----
    {
        unsigned dstBase = (unsigned)__cvta_generic_to_shared(&buf[wloc][0][lane]);
        #pragma unroll
        for (int j = 0; j < 8; j++) {
            unsigned idx = (unsigned)((j < 4)
                ? ((j == 0) ? xa.x : (j == 1) ? xa.y : (j == 2) ? xa.z : xa.w)
                : ((j == 4) ? xb.x : (j == 5) ? xb.y : (j == 6) ? xb.z : xb.w));
            const float4* src = gw + idx;
            unsigned dst = dstBase + (unsigned)(j * 32 * sizeof(float4));
            unsigned long long pol = (idx < PIN_ROWS) ? polLast : polNorm;
            asm volatile(
                "cp.async.cg.shared.global.L2::cache_hint [%0], [%1], 16, %2;"
                :: "r"(dst), "l"(src), "l"(pol) : "memory");
        }
    }
    asm volatile("cp.async.commit_group;" ::: "memory");

    // d: one coalesced float per lane (lanes 0..15 meaningful), broadcast below.
    const float* dr = dvec + (size_t)warp * 16;
    float dmine = __ldg(&dr[lane & 15]);

    // ---- overlap: per-ray direction part of layer 0 ----
    float base[8];
    #pragma unroll
    for (int k = 0; k < 8; k++) base[k] = 0.f;
    #pragma unroll
    for (int i = 0; i < 16; i++) {
        float dv = __shfl_sync(0xffffffffu, dmine, i);
        #pragma unroll
        for (int k = 0; k < 8; k++)
            base[k] = fmaf(dv, sW0[i * 8 + k], base[k]);
    }

    asm volatile("cp.async.wait_group 0;" ::: "memory");

    float sig[4];
    float acc0 = 0.f, acc1 = 0.f, acc2 = 0.f;
    float Tloc = 1.f;

    #pragma unroll
    for (int s = 0; s < 4; s++) {
        float4 a = buf[wloc][2 * s][lane];
        float4 b = buf[wloc][2 * s + 1][lane];

        float sg = 1.f / (1.f + __expf(-(a.x * b.x)));
        sig[s] = sg;

        // geo part of layer 0 + ReLU
        float h[8];
        #pragma unroll
        for (int k = 0; k < 8; k++) {
            float v = base[k];
            v = fmaf(a.y, sW0[16 * 8 + k], v);
            v = fmaf(a.z, sW0[17 * 8 + k], v);
            v = fmaf(a.w, sW0[18 * 8 + k], v);
            v = fmaf(b.y, sW0[19 * 8 + k], v);
            v = fmaf(b.z, sW0[20 * 8 + k], v);
            v = fmaf(b.w, sW0[21 * 8 + k], v);
            h[k] = fmaxf(v, 0.f);
        }

        // layer 1 + sigmoid
        float z0 = 0.f, z1 = 0.f, z2 = 0.f;
        #pragma unroll
        for (int k = 0; k < 8; k++) {
            z0 = fmaf(h[k], sW1[k * 3 + 0], z0);
            z1 = fmaf(h[k], sW1[k * 3 + 1], z1);
            z2 = fmaf(h[k], sW1[k * 3 + 2], z2);
        }
        float c0 = 1.f / (1.f + __expf(-z0));
        float c1 = 1.f / (1.f + __expf(-z1));
        float c2 = 1.f / (1.f + __expf(-z2));

        // local (within-lane) transmittance chain
        float w = Tloc * sg;
        acc0 = fmaf(w, c0, acc0);
        acc1 = fmaf(w, c1, acc1);
        acc2 = fmaf(w, c2, acc2);
        Tloc *= (1.f - sg);
    }

    // ---- warp exclusive product scan of per-lane (1-sigma) products ----
    float sp = Tloc;
    #pragma unroll
    for (int off = 1; off < 32; off <<= 1) {
        float v = __shfl_up_sync(0xffffffffu, sp, off);
        sp *= (lane >= off) ? v : 1.f;
    }
    float Tpre = __shfl_up_sync(0xffffffffu, sp, 1);
    Tpre = (lane == 0) ? 1.f : Tpre;

    acc0 *= Tpre; acc1 *= Tpre; acc2 *= Tpre;

    // ---- warp reduce rgb ----
    #pragma unroll
    for (int off = 16; off >= 1; off >>= 1) {
        acc0 += __shfl_down_sync(0xffffffffu, acc0, off);
        acc1 += __shfl_down_sync(0xffffffffu, acc1, off);
        acc2 += __shfl_down_sync(0xffffffffu, acc2, off);
    }

    // ---- stores ----
    ((float4*)(sigma_out + (size_t)warp * RAY_N))[lane] =
        make_float4(sig[0], sig[1], sig[2], sig[3]);
    if (lane == 0) {
        float* r = rgb_out + (size_t)warp * 3;
        r[0] = acc0; r[1] = acc1; r[2] = acc2;
    }
}

extern "C" void kernel_launch(void* const* d_in, const int* in_sizes, int n_in,
                              void* d_out, int out_size)
{
    const int*    x    = (const int*)d_in[0];
    const float*  dvec = (const float*)d_in[1];
    const float4* gw   = (const float4*)d_in[2];
    const float*  W0   = (const float*)d_in[3];
    const float*  W1   = (const float*)d_in[4];

    int B = in_sizes[1] / 16;                 // d is [B, 16]
    float* out   = (float*)d_out;
    float* sigma = out;                        // [B, 128]
    float* rgb   = out + (size_t)B * RAY_N;    // [B, 3]

    int blocks = (B + WPB - 1) / WPB;
    surf_kernel<<<blocks, 256>>>(x, dvec, gw, W0, W1, sigma, rgb, B);
}